// round 12
// baseline (speedup 1.0000x reference)
#include <cuda_runtime.h>

// B=128, N=1024. out[b,k] = a[b,j] - a[b,i], strict upper triangle (j>i),
// row-major pair order. Row i (len 1023-i) starts at off(i) = i*(2047-i)/2.
//
// One ROW-PAIR per warp (pair p = row p + row 1022-p = exactly 1024 outputs);
// 2 pairs per warp (16 pairs/block, grid 32x128) to amortize smem staging.
// R12: each pair runs as FOUR groups of 3 batches (2 long + 1 short) with
// __syncwarp() between groups. The syncwarp is a memory-ordering fence ptxas
// cannot hoist LDS across, so the live buffer set stays at 3 float4 ->
// ~45 regs -> ~2x the occupancy of R9/R11 (which hit 76-80 regs).

constexpr int N_ELEM  = 1024;
constexpr int M_PAIRS = N_ELEM * (N_ELEM - 1) / 2;   // 523776
constexpr int THREADS = 256;                          // 8 warps
constexpr int PAIRS_PER_WARP  = 2;
constexpr int PAIRS_PER_BLOCK = 8 * PAIRS_PER_WARP;   // 16
constexpr int PITCH   = N_ELEM + 4;                   // 16B-aligned copy pitch

__device__ __forceinline__ int row_off(int i) {
    return (i * (2047 - i)) >> 1;                     // exact (product even)
}

struct RowCtx {
    const float* src;   // aligned smem source (shifted copy)
    float* dst;         // aligned global dest
    int n4;             // aligned float4 count
    float ai;
};

__device__ __forceinline__ RowCtx row_setup(int i, const float* __restrict__ sh,
                                            float* __restrict__ outb, int lane) {
    const int start = row_off(i);
    const int len   = 1023 - i;
    const int end   = start + len;
    const float ai  = sh[i];                          // broadcast LDS

    const int astart = (start + 3) & ~3;
    const int aend   = end & ~3;

    // Head scalars (<=3 lanes)
    const int head_n = min(astart, end) - start;
    if (lane < head_n)
        outb[start + lane] = sh[i + 1 + lane] - ai;
    // Tail scalars (<=3 lanes)
    const int tstart = max(aend, astart);
    const int tail_n = end - tstart;
    if (lane < tail_n)
        outb[tstart + lane] = sh[i + 1 + (tstart - start) + lane] - ai;

    int n4 = (aend - astart) >> 2;
    if (n4 < 0) n4 = 0;
    const int jbase = i + 1 + (astart - start);
    const int r     = jbase & 3;

    RowCtx c;
    c.src = sh + r * PITCH + (jbase - r);
    c.dst = outb + astart;
    c.n4  = n4;
    c.ai  = ai;
    return c;
}

// One group: NL long-batches + NS short-batches. Loads batched (MLP), then
// compute + store.
template <int NL, int NS>
__device__ __forceinline__ void do_group(const RowCtx& L, const RowCtx& S,
                                         int lane, int uL0, int uS0) {
    float4 Lv[NL], Sv[NS];
    #pragma unroll
    for (int u = 0; u < NL; u++) {
        const int q = lane + 32 * (uL0 + u);
        if (q < L.n4)
            Lv[u] = *reinterpret_cast<const float4*>(L.src + (q << 2));
    }
    #pragma unroll
    for (int u = 0; u < NS; u++) {
        const int q = lane + 32 * (uS0 + u);
        if (q < S.n4)
            Sv[u] = *reinterpret_cast<const float4*>(S.src + (q << 2));
    }
    #pragma unroll
    for (int u = 0; u < NL; u++) {
        const int q = lane + 32 * (uL0 + u);
        if (q < L.n4) {
            const float4 v = Lv[u];
            *reinterpret_cast<float4*>(L.dst + (q << 2)) =
                make_float4(v.x - L.ai, v.y - L.ai, v.z - L.ai, v.w - L.ai);
        }
    }
    #pragma unroll
    for (int u = 0; u < NS; u++) {
        const int q = lane + 32 * (uS0 + u);
        if (q < S.n4) {
            const float4 v = Sv[u];
            *reinterpret_cast<float4*>(S.dst + (q << 2)) =
                make_float4(v.x - S.ai, v.y - S.ai, v.z - S.ai, v.w - S.ai);
        }
    }
}

__global__ __launch_bounds__(THREADS)
void relpos_kernel(const float* __restrict__ in, float* __restrict__ out) {
    // 4 shifted copies: sh[r*PITCH + m] = a[m + r]
    __shared__ float sh[4 * PITCH];

    const int b = blockIdx.y;
    const float* a = in + (size_t)b * N_ELEM;

    // Stage input + build shifted copies (one float4 per thread).
    {
        const float4 v = reinterpret_cast<const float4*>(a)[threadIdx.x];
        const int idx = threadIdx.x * 4;
        const float vv[4] = {v.x, v.y, v.z, v.w};
        #pragma unroll
        for (int e = 0; e < 4; e++) {
            const int x = idx + e;
            const float val = vv[e];
            #pragma unroll
            for (int r = 0; r < 4; r++) {
                const int m = x - r;
                if (m >= 0) sh[r * PITCH + m] = val;
            }
        }
    }
    __syncthreads();

    float* outb = out + (size_t)b * M_PAIRS;
    const int warp = threadIdx.x >> 5;
    const int lane = threadIdx.x & 31;

    #pragma unroll 1
    for (int sub = 0; sub < PAIRS_PER_WARP; sub++) {
        const int p = blockIdx.x * PAIRS_PER_BLOCK + warp + 8 * sub; // 0..511
        const int iS = 1022 - p;

        RowCtx L = row_setup(p, sh, outb, lane);
        RowCtx S;
        S.n4 = 0; S.ai = 0.f; S.src = sh; S.dst = outb;
        if (p < 511) S = row_setup(iS, sh, outb, lane);
        __syncwarp();

        // Four fenced groups of 3 batches (2 long + 1 short each):
        // live float4 buffers capped at 3 -> small register footprint.
        do_group<2, 1>(L, S, lane, 0, 0);
        __syncwarp();
        do_group<2, 1>(L, S, lane, 2, 1);
        __syncwarp();
        do_group<2, 1>(L, S, lane, 4, 2);
        __syncwarp();
        do_group<2, 1>(L, S, lane, 6, 3);
        __syncwarp();
    }
}

extern "C" void kernel_launch(void* const* d_in, const int* in_sizes, int n_in,
                              void* d_out, int out_size) {
    const float* in = (const float*)d_in[0];
    float* out = (float*)d_out;
    const int B = in_sizes[0] / N_ELEM;               // 128

    dim3 grid(512 / PAIRS_PER_BLOCK, B);              // (32, 128)
    relpos_kernel<<<grid, THREADS>>>(in, out);
}

// round 13
// speedup vs baseline: 1.0566x; 1.0566x over previous
#include <cuda_runtime.h>

// B=128, N=1024. out[b,k] = a[b,j] - a[b,i], strict upper triangle (j>i),
// row-major pair order. Row i (len 1023-i) starts at off(i) = i*(2047-i)/2.
//
// One ROW-PAIR per warp (pair p = row p + row 1022-p = exactly 1024 outputs);
// 2 pairs per warp (16 pairs/block, grid 32x128) to amortize smem staging.
// R13: rows processed by a ROLLED warp-stride loop, unroll x2 in-body (MLP 2,
// 2 live buffers, pointer-bumped addresses). This denies ptxas the chance to
// precompute 12 batches of 64-bit addresses (the real source of R9-R12's
// 76-80 regs) -> ~36 regs -> high occupancy covers the LDS/STG latency.

constexpr int N_ELEM  = 1024;
constexpr int M_PAIRS = N_ELEM * (N_ELEM - 1) / 2;   // 523776
constexpr int THREADS = 256;                          // 8 warps
constexpr int PAIRS_PER_WARP  = 2;
constexpr int PAIRS_PER_BLOCK = 8 * PAIRS_PER_WARP;   // 16
constexpr int PITCH   = N_ELEM + 4;                   // 16B-aligned copy pitch

__device__ __forceinline__ int row_off(int i) {
    return (i * (2047 - i)) >> 1;                     // exact (product even)
}

__device__ __forceinline__ void process_row(int i, const float* __restrict__ sh,
                                            float* __restrict__ outb, int lane) {
    const int start = row_off(i);
    const int len   = 1023 - i;
    const int end   = start + len;
    const float ai  = sh[i];                          // broadcast LDS

    const int astart = (start + 3) & ~3;
    const int aend   = end & ~3;

    // Head scalars (<=3 lanes)
    const int head_n = min(astart, end) - start;
    if (lane < head_n)
        outb[start + lane] = sh[i + 1 + lane] - ai;
    // Tail scalars (<=3 lanes)
    const int tstart = max(aend, astart);
    const int tail_n = end - tstart;
    if (lane < tail_n)
        outb[tstart + lane] = sh[i + 1 + (tstart - start) + lane] - ai;

    int n4 = (aend - astart) >> 2;
    if (n4 < 0) n4 = 0;
    const int jbase = i + 1 + (astart - start);
    const int r     = jbase & 3;
    const float* __restrict__ src = sh + r * PITCH + (jbase - r);
    float* __restrict__ dst = outb + astart;

    // Rolled warp-stride loop, 2 batches per iteration (MLP 2).
    #pragma unroll 1
    for (int q = lane; q < n4; q += 64) {
        const float4 v0 = *reinterpret_cast<const float4*>(src + (q << 2));
        const bool p1 = (q + 32) < n4;
        float4 v1;
        if (p1)
            v1 = *reinterpret_cast<const float4*>(src + ((q + 32) << 2));

        *reinterpret_cast<float4*>(dst + (q << 2)) =
            make_float4(v0.x - ai, v0.y - ai, v0.z - ai, v0.w - ai);
        if (p1)
            *reinterpret_cast<float4*>(dst + ((q + 32) << 2)) =
                make_float4(v1.x - ai, v1.y - ai, v1.z - ai, v1.w - ai);
    }
}

__global__ __launch_bounds__(THREADS)
void relpos_kernel(const float* __restrict__ in, float* __restrict__ out) {
    // 4 shifted copies: sh[r*PITCH + m] = a[m + r]
    __shared__ float sh[4 * PITCH];

    const int b = blockIdx.y;
    const float* a = in + (size_t)b * N_ELEM;

    // Stage input + build shifted copies (one float4 per thread).
    {
        const float4 v = reinterpret_cast<const float4*>(a)[threadIdx.x];
        const int idx = threadIdx.x * 4;
        const float vv[4] = {v.x, v.y, v.z, v.w};
        #pragma unroll
        for (int e = 0; e < 4; e++) {
            const int x = idx + e;
            const float val = vv[e];
            #pragma unroll
            for (int r = 0; r < 4; r++) {
                const int m = x - r;
                if (m >= 0) sh[r * PITCH + m] = val;
            }
        }
    }
    __syncthreads();

    float* outb = out + (size_t)b * M_PAIRS;
    const int warp = threadIdx.x >> 5;
    const int lane = threadIdx.x & 31;

    #pragma unroll 1
    for (int sub = 0; sub < PAIRS_PER_WARP; sub++) {
        const int p = blockIdx.x * PAIRS_PER_BLOCK + warp + 8 * sub; // 0..511
        process_row(p, sh, outb, lane);                // long row (len 1023-p)
        if (p < 511)
            process_row(1022 - p, sh, outb, lane);     // short row (len p+1)
    }
}

extern "C" void kernel_launch(void* const* d_in, const int* in_sizes, int n_in,
                              void* d_out, int out_size) {
    const float* in = (const float*)d_in[0];
    float* out = (float*)d_out;
    const int B = in_sizes[0] / N_ELEM;               // 128

    dim3 grid(512 / PAIRS_PER_BLOCK, B);              // (32, 128)
    relpos_kernel<<<grid, THREADS>>>(in, out);
}